// round 10
// baseline (speedup 1.0000x reference)
#include <cuda_runtime.h>
#include <cuda_bf16.h>
#include <math.h>

#define Bn 4096
#define Kn 3000
#define KP 3072            /* padded row stride (bf16 elems)       */
#define NBS 148            /* blocks per slot                      */
#define NB2 296            /* total persistent blocks              */
#define NT 256
#define NTIL 512           /* 8-row tiles (512*8 = 4096)           */
#define NCG 4              /* chunk-groups in partial reduce       */
#define CPG 37             /* chunks per group (4*37 = 148)        */

#define TINYF 1e-12f
#define TOLF  1e-3f
#define INV_EPS 20.0f      /* 1/0.05 */
#define INV_TEMP 10.0f     /* 1/0.1  */
#define TC 1.3653333333333333f   /* 4096/3000 */

static __device__ __align__(16) __nv_bfloat16 g_Qh[2][(size_t)Bn * KP]; // ~50 MB
static __device__ float    g_u[2][2][Bn];
static __device__ float    g_r[2][Bn];
static __device__ float    g_w1[2][Bn];
static __device__ float    g_alpha[2][Bn];
static __device__ __align__(16) float g_beta[2][Kn];
static __device__ __align__(16) float g_t2[2][2][(size_t)NBS * KP];  // per-block col partials
static __device__ __align__(16) float g_vp[2][NCG][KP];              // 4-way partial sums
static __device__ __align__(16) float g_vp2[2][NCG][KP];             // (cs partials, post)
static __device__ unsigned g_rowerr[2][104];
static __device__ unsigned g_colerr[2][104];
static __device__ float    g_ent[2];
static __device__ float    g_qmax[2];
static __device__ float    g_loss;
static __device__ unsigned g_bar_count;
static __device__ unsigned g_bar_gen;

struct Ptrs { const float* p[8]; };

// ---------------- grid barrier (296 resident blocks) ------------------------
static __device__ __forceinline__ void grid_sync()
{
    __syncthreads();
    if (threadIdx.x == 0) {
        volatile unsigned* vgen = &g_bar_gen;
        unsigned gen = *vgen;
        __threadfence();
        unsigned t = atomicAdd(&g_bar_count, 1u);
        if (t == (unsigned)NB2 - 1u) {
            g_bar_count = 0u;
            __threadfence();
            *vgen = gen + 1u;
        } else {
            while (*vgen == gen) { __nanosleep(20); }
        }
        __threadfence();   // CCTL.IVALL -> drop stale L1 lines for whole SM
    }
    __syncthreads();
}

// ---------------- init ------------------------------------------------------
__global__ void init_kernel()
{
    if (threadIdx.x == 0) {
        g_loss = 0.f;
        g_ent[0] = g_ent[1] = 0.f;
        g_qmax[0] = g_qmax[1] = 0.f;
        g_bar_count = 0u;
    }
}

// ---------------- prep: Qh = bf16(exp(S - rowmax)), padded, vectorized ------
__global__ __launch_bounds__(NT) void prep_kernel(Ptrs ptrs, const int* pia, const int* pib)
{
    __shared__ float wmax[8];
    int b = blockIdx.x & (Bn - 1);
    int s = blockIdx.x >> 12;
    int id = (s == 0) ? *pia : *pib;
    const float* lg = ptrs.p[id] + (size_t)b * Kn;
    const float4* lg4 = (const float4*)lg;
    int tid = threadIdx.x, lane = tid & 31, wid = tid >> 5;

    float mx = -3.4e38f;
    for (int i = tid; i < Kn / 4; i += NT) {
        float4 x = lg4[i];
        mx = fmaxf(mx, fmaxf(fmaxf(x.x, x.y), fmaxf(x.z, x.w)));
    }
    #pragma unroll
    for (int o = 16; o; o >>= 1) mx = fmaxf(mx, __shfl_xor_sync(0xffffffffu, mx, o));
    if (lane == 0) wmax[wid] = mx;
    __syncthreads();
    float bm = wmax[0];
    #pragma unroll
    for (int w = 1; w < 8; ++w) bm = fmaxf(bm, wmax[w]);
    float m = bm * INV_EPS;

    uint2* qh = (uint2*)(g_Qh[s] + (size_t)b * KP);
    for (int i = tid; i < KP / 4; i += NT) {
        uint2 st;
        if (i < Kn / 4) {
            float4 x = lg4[i];
            __nv_bfloat162 h0 = __floats2bfloat162_rn(__expf(x.x * INV_EPS - m),
                                                      __expf(x.y * INV_EPS - m));
            __nv_bfloat162 h1 = __floats2bfloat162_rn(__expf(x.z * INV_EPS - m),
                                                      __expf(x.w * INV_EPS - m));
            st.x = *(unsigned*)&h0; st.y = *(unsigned*)&h1;
        } else { st.x = 0u; st.y = 0u; }
        qh[i] = st;
    }
}

// ---------------- helpers ---------------------------------------------------
static __device__ __forceinline__ float row_dot(const __nv_bfloat16* qrow,
                                                const float4* s4, int lane)
{
    const uint4* qr = (const uint4*)qrow;
    float acc = 0.f;
    #pragma unroll
    for (int j = 0; j < 12; ++j) {
        int idx = j * 32 + lane;
        uint4 q = qr[idx];
        float4 sa = s4[idx * 2], sb = s4[idx * 2 + 1];
        float2 f0 = __bfloat1622float2(*reinterpret_cast<__nv_bfloat162*>(&q.x));
        float2 f1 = __bfloat1622float2(*reinterpret_cast<__nv_bfloat162*>(&q.y));
        float2 f2 = __bfloat1622float2(*reinterpret_cast<__nv_bfloat162*>(&q.z));
        float2 f3 = __bfloat1622float2(*reinterpret_cast<__nv_bfloat162*>(&q.w));
        acc += f0.x * sa.x + f0.y * sa.y + f1.x * sa.z + f1.y * sa.w
             + f2.x * sb.x + f2.y * sb.y + f3.x * sb.z + f3.y * sb.w;
    }
    return acc;
}

// phase-2: accumulate u_b * Q[b, kslice] for an 8-row tile into warp-private
// smem slice [wbase, wbase+384). L1-hot re-read of the tile. No atomics.
static __device__ __forceinline__ void tile_colacc(const __nv_bfloat16* tb,
                                                   const float* su8, float* sacc,
                                                   int wbase, int lane)
{
    float a[12];
    #pragma unroll
    for (int e = 0; e < 12; ++e) a[e] = 0.f;
    #pragma unroll
    for (int rr = 0; rr < 8; ++rr) {
        float uu = su8[rr];
        const uint2* rp = (const uint2*)(tb + (size_t)rr * KP);
        #pragma unroll
        for (int j = 0; j < 3; ++j) {
            uint2 qv = rp[j * 32 + lane];
            float2 f0 = __bfloat1622float2(*(__nv_bfloat162*)&qv.x);
            float2 f1 = __bfloat1622float2(*(__nv_bfloat162*)&qv.y);
            a[j*4+0] += uu * f0.x; a[j*4+1] += uu * f0.y;
            a[j*4+2] += uu * f1.x; a[j*4+3] += uu * f1.y;
        }
    }
    #pragma unroll
    for (int j = 0; j < 3; ++j) {
        float4* sp = (float4*)&sacc[wbase + j * 128 + lane * 4];
        float4 cur = *sp;
        cur.x += a[j*4+0]; cur.y += a[j*4+1];
        cur.z += a[j*4+2]; cur.w += a[j*4+3];
        *sp = cur;
    }
}

// ---------------- fused persistent Sinkhorn (both crops) --------------------
__global__ __launch_bounds__(NT, 2) void sinkhorn_fused()
{
    __shared__ __align__(16) float sv[KP];
    __shared__ __align__(16) float sacc[KP];
    __shared__ float su8[8];
    __shared__ float swr[8];
    __shared__ float sqr[8];

    const int tid = threadIdx.x, bid = blockIdx.x;
    const int lane = tid & 31, wid = tid >> 5;
    const int slot = (bid >= NBS) ? 1 : 0;
    const int sbid = bid - slot * NBS;
    const __nv_bfloat16* Qs = g_Qh[slot];
    const int wbase = wid * 384;

    {   // zero err arrays
        int i = sbid * NT + tid;
        if (i < 104) { g_rowerr[slot][i] = 0u; g_colerr[slot][i] = 0u; }
    }
    grid_sync();

    bool done0 = false, done1 = false;
    int nfin0 = 100, nfin1 = 100;

    for (int iter = 1; iter <= 100; ++iter) {
        const int par = iter & 1, pprev = par ^ 1;
        const bool act = slot ? !done1 : !done0;

        // ---- stage A: 148 chunks -> 4 partial groups (12 blocks/slot) ----
        if (act && iter >= 2 && sbid < 12) {
            int kg = sbid % 3, cg = sbid / 3;
            int i4 = kg * NT + tid;                 // float4 index 0..767
            const float4* tp = (const float4*)(g_t2[slot][pprev])
                               + (size_t)(cg * CPG) * (KP / 4) + i4;
            float4 s = make_float4(0.f, 0.f, 0.f, 0.f);
            #pragma unroll 8
            for (int c = 0; c < CPG; ++c) {
                float4 x = tp[(size_t)c * (KP / 4)];
                s.x += x.x; s.y += x.y; s.z += x.z; s.w += x.w;
            }
            ((float4*)g_vp[slot][cg])[i4] = s;
        }
        grid_sync();

        if (act) {
            // ---- sv fill from 4 partials (+ col_err by block 0) ----
            float ce = 0.f;
            if (iter == 1) {
                for (int i = tid; i < KP / 4; i += NT)
                    ((float4*)sv)[i] = (i < Kn / 4) ? make_float4(1.f, 1.f, 1.f, 1.f)
                                                    : make_float4(0.f, 0.f, 0.f, 0.f);
            } else {
                for (int i = tid; i < KP / 4; i += NT) {
                    float4 t0 = ((const float4*)g_vp[slot][0])[i];
                    float4 t1 = ((const float4*)g_vp[slot][1])[i];
                    float4 t2v = ((const float4*)g_vp[slot][2])[i];
                    float4 t3 = ((const float4*)g_vp[slot][3])[i];
                    float tx = t0.x + t1.x + t2v.x + t3.x;
                    float ty = t0.y + t1.y + t2v.y + t3.y;
                    float tz = t0.z + t1.z + t2v.z + t3.z;
                    float tw = t0.w + t1.w + t2v.w + t3.w;
                    float4 v4;
                    v4.x = TC / (tx + TINYF); v4.y = TC / (ty + TINYF);
                    v4.z = TC / (tz + TINYF); v4.w = TC / (tw + TINYF);
                    if (i < Kn / 4) {
                        ((float4*)sv)[i] = v4;
                        if (sbid == 0) {
                            ce = fmaxf(ce, fabsf(v4.x * tx - TC));
                            ce = fmaxf(ce, fabsf(v4.y * ty - TC));
                            ce = fmaxf(ce, fabsf(v4.z * tz - TC));
                            ce = fmaxf(ce, fabsf(v4.w * tw - TC));
                        }
                    } else ((float4*)sv)[i] = make_float4(0.f, 0.f, 0.f, 0.f);
                }
            }
            if (sbid == 0 && iter >= 2) {
                #pragma unroll
                for (int o = 16; o; o >>= 1)
                    ce = fmaxf(ce, __shfl_xor_sync(0xffffffffu, ce, o));
                if (lane == 0 && ce > 0.f)
                    atomicMax(&g_colerr[slot][iter - 1], __float_as_uint(ce));
            }
            for (int i = tid; i < KP / 4; i += NT)
                ((float4*)sacc)[i] = make_float4(0.f, 0.f, 0.f, 0.f);
            __syncthreads();

            // ---- tiles: phase1 rows (L2) + phase2 col partials (L1-hot) ----
            float remax = 0.f;
            const float4* s4 = (const float4*)sv;
            for (int tile = sbid; tile < NTIL; tile += NBS) {
                int row = tile * 8 + wid;
                float acc = row_dot(Qs + (size_t)row * KP, s4, lane);
                #pragma unroll
                for (int o = 16; o; o >>= 1)
                    acc += __shfl_xor_sync(0xffffffffu, acc, o);
                if (lane == 0) {
                    g_r[slot][row] = acc;
                    float uu = 1.f / (acc + TINYF);
                    g_u[slot][par][row] = uu;
                    su8[wid] = uu;
                    if (iter >= 2)
                        remax = fmaxf(remax, fabsf(g_u[slot][pprev][row] * acc - 1.f));
                }
                __syncthreads();
                tile_colacc(Qs + (size_t)(tile * 8) * KP + wbase, su8, sacc, wbase, lane);
                __syncthreads();
            }
            {   // write this block's column-partial chunk
                float4* dst = (float4*)(g_t2[slot][par] + (size_t)sbid * KP);
                const float4* src = (const float4*)sacc;
                for (int i = tid; i < KP / 4; i += NT) dst[i] = src[i];
            }
            if (lane == 0) swr[wid] = remax;
            __syncthreads();
            if (tid == 0 && iter >= 2) {
                float m = swr[0];
                #pragma unroll
                for (int w = 1; w < 8; ++w) m = fmaxf(m, swr[w]);
                if (m > 0.f) atomicMax(&g_rowerr[slot][iter - 1], __float_as_uint(m));
            }
        }
        grid_sync();

        // ---- convergence: identical global data -> uniform decision ----
        if (iter >= 2) {
            int it = iter - 1;
            if (!done0) {
                float e = fmaxf(__uint_as_float(g_rowerr[0][it]),
                                __uint_as_float(g_colerr[0][it]));
                if (it >= 3 && e <= TOLF) { done0 = true; nfin0 = it; }
            }
            if (!done1) {
                float e = fmaxf(__uint_as_float(g_rowerr[1][it]),
                                __uint_as_float(g_colerr[1][it]));
                if (it >= 3 && e <= TOLF) { done1 = true; nfin1 = it; }
            }
        }
        if (!done0 && iter >= 100) { done0 = true; nfin0 = 100; }
        if (!done1 && iter >= 100) { done1 = true; nfin1 = 100; }
        if (done0 && done1) break;
    }

    const int nfin = slot ? nfin1 : nfin0;
    const int p = nfin & 1;

    // ---- P0: w1_b = u_b / max(u_b*r_b, TINY) ----
    if (sbid < 16) {
        int b = sbid * NT + tid;
        float u = g_u[slot][p][b], r = g_r[slot][b];
        g_w1[slot][b] = u / fmaxf(u * r, TINYF);
    }
    grid_sync();

    // ---- P1: column sums of row-normalized P -> t2[1-p] (tile-based) ----
    {
        for (int i = tid; i < KP / 4; i += NT)
            ((float4*)sacc)[i] = make_float4(0.f, 0.f, 0.f, 0.f);
        __syncthreads();
        for (int tile = sbid; tile < NTIL; tile += NBS) {
            if (tid < 8) su8[tid] = g_w1[slot][tile * 8 + tid];
            __syncthreads();
            tile_colacc(Qs + (size_t)(tile * 8) * KP + wbase, su8, sacc, wbase, lane);
            __syncthreads();
        }
        float4* dst = (float4*)(g_t2[slot][1 - p] + (size_t)sbid * KP);
        for (int i = tid; i < KP / 4; i += NT) dst[i] = ((float4*)sacc)[i];
    }
    grid_sync();

    // ---- beta partials: both parities, 148 -> 4 groups (12 blocks/slot) ----
    if (sbid < 12) {
        int kg = sbid % 3, cg = sbid / 3;
        int i4 = kg * NT + tid;
        const float4* tp = (const float4*)(g_t2[slot][p])
                           + (size_t)(cg * CPG) * (KP / 4) + i4;
        const float4* cp = (const float4*)(g_t2[slot][1 - p])
                           + (size_t)(cg * CPG) * (KP / 4) + i4;
        float4 at = make_float4(0.f, 0.f, 0.f, 0.f);
        float4 ac = make_float4(0.f, 0.f, 0.f, 0.f);
        #pragma unroll 4
        for (int c = 0; c < CPG; ++c) {
            float4 x = tp[(size_t)c * (KP / 4)];
            float4 y = cp[(size_t)c * (KP / 4)];
            at.x += x.x; at.y += x.y; at.z += x.z; at.w += x.w;
            ac.x += y.x; ac.y += y.y; ac.z += y.z; ac.w += y.w;
        }
        ((float4*)g_vp[slot][cg])[i4] = at;
        ((float4*)g_vp2[slot][cg])[i4] = ac;
    }
    grid_sync();

    // ---- beta final (3 blocks/slot) ----
    if (sbid < 3) {
        int i4 = sbid * NT + tid;
        if (i4 < Kn / 4) {
            float4 t0 = ((const float4*)g_vp[slot][0])[i4];
            float4 t1 = ((const float4*)g_vp[slot][1])[i4];
            float4 t2v = ((const float4*)g_vp[slot][2])[i4];
            float4 t3 = ((const float4*)g_vp[slot][3])[i4];
            float4 c0 = ((const float4*)g_vp2[slot][0])[i4];
            float4 c1 = ((const float4*)g_vp2[slot][1])[i4];
            float4 c2 = ((const float4*)g_vp2[slot][2])[i4];
            float4 c3 = ((const float4*)g_vp2[slot][3])[i4];
            float t[4]  = { t0.x + t1.x + t2v.x + t3.x, t0.y + t1.y + t2v.y + t3.y,
                            t0.z + t1.z + t2v.z + t3.z, t0.w + t1.w + t2v.w + t3.w };
            float cs[4] = { c0.x + c1.x + c2.x + c3.x, c0.y + c1.y + c2.y + c3.y,
                            c0.z + c1.z + c2.z + c3.z, c0.w + c1.w + c2.w + c3.w };
            float4 bb;
            float* bp = (float*)&bb;
            #pragma unroll
            for (int e = 0; e < 4; ++e) {
                float v = TC / (t[e] + TINYF);
                float c = v * cs[e];
                bp[e] = v * (TC / fmaxf(c, TINYF));
            }
            ((float4*)g_beta[slot])[i4] = bb;
        }
    }
    grid_sync();

    // ---- P2: alpha, entropy, q_max ----
    for (int k = tid; k < KP; k += NT)
        sv[k] = (k < Kn) ? g_beta[slot][k] : 0.f;
    __syncthreads();

    float entacc = 0.f, qsum = 0.f;
    const float4* s4 = (const float4*)sv;
    for (int row = sbid * 8 + wid; row < Bn; row += NBS * 8) {
        float s2 = row_dot(Qs + (size_t)row * KP, s4, lane);
        #pragma unroll
        for (int o = 16; o; o >>= 1)
            s2 += __shfl_xor_sync(0xffffffffu, s2, o);
        float w1 = g_w1[slot][row];
        float alpha = w1 / fmaxf(w1 * s2, TINYF);
        if (lane == 0) g_alpha[slot][row] = alpha;

        const uint4* qr = (const uint4*)(Qs + (size_t)row * KP);
        float qm = 0.f;
        #pragma unroll 4
        for (int j = 0; j < 12; ++j) {
            int idx = j * 32 + lane;
            uint4 q = qr[idx];
            float4 sa = s4[idx * 2], sb = s4[idx * 2 + 1];
            float2 f0 = __bfloat1622float2(*reinterpret_cast<__nv_bfloat162*>(&q.x));
            float2 f1 = __bfloat1622float2(*reinterpret_cast<__nv_bfloat162*>(&q.y));
            float2 f2 = __bfloat1622float2(*reinterpret_cast<__nv_bfloat162*>(&q.z));
            float2 f3 = __bfloat1622float2(*reinterpret_cast<__nv_bfloat162*>(&q.w));
            float pe[8] = { f0.x * sa.x, f0.y * sa.y, f1.x * sa.z, f1.y * sa.w,
                            f2.x * sb.x, f2.y * sb.y, f3.x * sb.z, f3.y * sb.w };
            #pragma unroll
            for (int e = 0; e < 8; ++e) {
                float p3 = alpha * pe[e];
                entacc += p3 * __logf(p3 + TINYF);
                qm = fmaxf(qm, p3);
            }
        }
        #pragma unroll
        for (int o = 16; o; o >>= 1)
            qm = fmaxf(qm, __shfl_xor_sync(0xffffffffu, qm, o));
        if (lane == 0) qsum += qm;
    }
    #pragma unroll
    for (int o = 16; o; o >>= 1)
        entacc += __shfl_xor_sync(0xffffffffu, entacc, o);
    __syncthreads();
    if (lane == 0) { swr[wid] = entacc; sqr[wid] = qsum; }
    __syncthreads();
    if (tid == 0) {
        float e = 0.f, q = 0.f;
        #pragma unroll
        for (int w = 0; w < 8; ++w) { e += swr[w]; q += sqr[w]; }
        atomicAdd(&g_ent[slot], e);
        atomicAdd(&g_qmax[slot], q);
    }
}

// ---------------- loss over all 8 crops (vectorized) ------------------------
__global__ __launch_bounds__(NT) void loss_kernel(Ptrs ptrs, const int* pia, const int* pib)
{
    __shared__ __align__(16) float pa[Kn];
    __shared__ __align__(16) float pb[Kn];
    __shared__ float wtmp[8];
    __shared__ float ws0[8], ws1[8], ws2[8];
    int b = blockIdx.x, tid = threadIdx.x;
    int lane = tid & 31, wid = tid >> 5;
    int ia = *pia, ib = *pib;

    float aA = g_alpha[0][b], aB = g_alpha[1][b];
    const uint2* q0 = (const uint2*)(g_Qh[0] + (size_t)b * KP);
    const uint2* q1 = (const uint2*)(g_Qh[1] + (size_t)b * KP);
    const float4* be0 = (const float4*)g_beta[0];
    const float4* be1 = (const float4*)g_beta[1];
    for (int i = tid; i < Kn / 4; i += NT) {
        uint2 v0 = q0[i], v1 = q1[i];
        float4 b0 = be0[i], b1 = be1[i];
        float2 f00 = __bfloat1622float2(*(__nv_bfloat162*)&v0.x);
        float2 f01 = __bfloat1622float2(*(__nv_bfloat162*)&v0.y);
        float2 f10 = __bfloat1622float2(*(__nv_bfloat162*)&v1.x);
        float2 f11 = __bfloat1622float2(*(__nv_bfloat162*)&v1.y);
        ((float4*)pa)[i] = make_float4(aA * f00.x * b0.x, aA * f00.y * b0.y,
                                       aA * f01.x * b0.z, aA * f01.y * b0.w);
        ((float4*)pb)[i] = make_float4(aB * f10.x * b1.x, aB * f10.y * b1.y,
                                       aB * f11.x * b1.z, aB * f11.y * b1.w);
    }
    __syncthreads();

    float accLoss = 0.f;
    for (int c = 0; c < 8; ++c) {
        const float4* lr4 = (const float4*)(ptrs.p[c] + (size_t)b * Kn);
        float mx = -3.4e38f;
        for (int i = tid; i < Kn / 4; i += NT) {
            float4 x = lr4[i];
            mx = fmaxf(mx, fmaxf(fmaxf(x.x, x.y), fmaxf(x.z, x.w)));
        }
        #pragma unroll
        for (int o = 16; o; o >>= 1) mx = fmaxf(mx, __shfl_xor_sync(0xffffffffu, mx, o));
        if (lane == 0) wtmp[wid] = mx;
        __syncthreads();
        float bm = wtmp[0];
        #pragma unroll
        for (int w = 1; w < 8; ++w) bm = fmaxf(bm, wtmp[w]);

        float se = 0.f, da = 0.f, db = 0.f;
        for (int i = tid; i < Kn / 4; i += NT) {
            float4 x = lr4[i];
            se += __expf(INV_TEMP * (x.x - bm)) + __expf(INV_TEMP * (x.y - bm))
                + __expf(INV_TEMP * (x.z - bm)) + __expf(INV_TEMP * (x.w - bm));
            float4 pav = ((const float4*)pa)[i];
            float4 pbv = ((const float4*)pb)[i];
            da += pav.x * x.x + pav.y * x.y + pav.z * x.z + pav.w * x.w;
            db += pbv.x * x.x + pbv.y * x.y + pbv.z * x.z + pbv.w * x.w;
        }
        #pragma unroll
        for (int o = 16; o; o >>= 1) {
            se += __shfl_xor_sync(0xffffffffu, se, o);
            da += __shfl_xor_sync(0xffffffffu, da, o);
            db += __shfl_xor_sync(0xffffffffu, db, o);
        }
        if (lane == 0) { ws0[wid] = se; ws1[wid] = da; ws2[wid] = db; }
        __syncthreads();
        if (tid == 0) {
            float st = 0.f, dat = 0.f, dbt = 0.f;
            #pragma unroll
            for (int w = 0; w < 8; ++w) { st += ws0[w]; dat += ws1[w]; dbt += ws2[w]; }
            float lse = INV_TEMP * bm + __logf(st);
            if (c != ia) accLoss += INV_TEMP * dat - lse;
            if (c != ib) accLoss += INV_TEMP * dbt - lse;
        }
        __syncthreads();
    }
    if (tid == 0) atomicAdd(&g_loss, accLoss);
}

// ---------------- finalize --------------------------------------------------
__global__ void finalize_kernel(float* out, int out_size)
{
    if (threadIdx.x == 0) {
        float loss = -g_loss / (14.f * (float)Bn);
        float ent  = -0.5f * (g_ent[0] + g_ent[1]) / (float)Bn;
        float qm   =  0.5f * (g_qmax[0] + g_qmax[1]) / (float)Bn;
        if (out_size > 0) out[0] = loss;
        if (out_size > 1) out[1] = ent;
        if (out_size > 2) out[2] = qm;
    }
}

// ---------------- launcher --------------------------------------------------
extern "C" void kernel_launch(void* const* d_in, const int* in_sizes, int n_in,
                              void* d_out, int out_size)
{
    (void)in_sizes; (void)n_in;
    Ptrs ptrs;
    for (int i = 0; i < 8; ++i) ptrs.p[i] = (const float*)d_in[i];
    const int* ia = (const int*)d_in[8];
    const int* ib = (const int*)d_in[9];

    init_kernel<<<1, 32>>>();
    prep_kernel<<<2 * Bn, NT>>>(ptrs, ia, ib);
    sinkhorn_fused<<<NB2, NT>>>();
    loss_kernel<<<Bn, NT>>>(ptrs, ia, ib);
    finalize_kernel<<<1, 32>>>((float*)d_out, out_size);
}

// round 11
// speedup vs baseline: 1.5820x; 1.5820x over previous
#include <cuda_runtime.h>
#include <cuda_bf16.h>
#include <math.h>

#define Bn 4096
#define Kn 3000
#define KP 3072            /* padded row stride (bf16 elems)            */
#define NBB 148            /* persistent blocks (512 thr, 2 halves)     */
#define NT 256             /* threads per half                          */
#define NCH 48             /* col-pass row chunks                       */
#define CTIL 3             /* col-pass k tiles (1024 cols each)         */
#define RPC 86             /* rows per chunk ceil(4096/48)              */

#define TINYF 1e-12f
#define TOLF  1e-3f
#define INV_EPS 20.0f      /* 1/0.05 */
#define INV_TEMP 10.0f     /* 1/0.1  */
#define TC 1.3653333333333333f   /* 4096/3000 */

static __device__ __align__(16) __nv_bfloat16 g_Qh[2][(size_t)Bn * KP]; // ~50 MB
static __device__ float    g_u[2][2][Bn];
static __device__ float    g_r[2][Bn];
static __device__ float    g_w1[2][Bn];
static __device__ float    g_alpha[2][Bn];
static __device__ __align__(16) float g_beta[2][Kn];
static __device__ __align__(16) float g_v[2][Kn];
static __device__ __align__(16) float g_tpart[2][2][(size_t)NCH * KP];
static __device__ unsigned g_rowerr[2][104];
static __device__ unsigned g_colerr[2][104];
static __device__ float    g_ent[2];
static __device__ float    g_qmax[2];
static __device__ float    g_loss;
static __device__ unsigned g_bar_count;
static __device__ unsigned g_bar_gen;

struct Ptrs { const float* p[8]; };

// ---------------- grid barrier (148 resident blocks) ------------------------
static __device__ __forceinline__ void grid_sync()
{
    __syncthreads();
    if (threadIdx.x == 0) {
        volatile unsigned* vgen = &g_bar_gen;
        unsigned gen = *vgen;
        __threadfence();
        unsigned t = atomicAdd(&g_bar_count, 1u);
        if (t == (unsigned)NBB - 1u) {
            g_bar_count = 0u;
            __threadfence();
            *vgen = gen + 1u;
        } else {
            while (*vgen == gen) { __nanosleep(20); }
        }
        __threadfence();   // CCTL.IVALL -> drop stale L1 lines for whole SM
    }
    __syncthreads();
}

// ---------------- init ------------------------------------------------------
__global__ void init_kernel()
{
    if (threadIdx.x == 0) {
        g_loss = 0.f;
        g_ent[0] = g_ent[1] = 0.f;
        g_qmax[0] = g_qmax[1] = 0.f;
        g_bar_count = 0u;
    }
}

// ---------------- prep: Qh = bf16(exp(S - rowmax)), padded, vectorized ------
__global__ __launch_bounds__(NT) void prep_kernel(Ptrs ptrs, const int* pia, const int* pib)
{
    __shared__ float wmax[8];
    int b = blockIdx.x & (Bn - 1);
    int s = blockIdx.x >> 12;
    int id = (s == 0) ? *pia : *pib;
    const float* lg = ptrs.p[id] + (size_t)b * Kn;
    const float4* lg4 = (const float4*)lg;
    int tid = threadIdx.x, lane = tid & 31, wid = tid >> 5;

    float mx = -3.4e38f;
    for (int i = tid; i < Kn / 4; i += NT) {
        float4 x = lg4[i];
        mx = fmaxf(mx, fmaxf(fmaxf(x.x, x.y), fmaxf(x.z, x.w)));
    }
    #pragma unroll
    for (int o = 16; o; o >>= 1) mx = fmaxf(mx, __shfl_xor_sync(0xffffffffu, mx, o));
    if (lane == 0) wmax[wid] = mx;
    __syncthreads();
    float bm = wmax[0];
    #pragma unroll
    for (int w = 1; w < 8; ++w) bm = fmaxf(bm, wmax[w]);
    float m = bm * INV_EPS;

    uint2* qh = (uint2*)(g_Qh[s] + (size_t)b * KP);
    for (int i = tid; i < KP / 4; i += NT) {
        uint2 st;
        if (i < Kn / 4) {
            float4 x = lg4[i];
            __nv_bfloat162 h0 = __floats2bfloat162_rn(__expf(x.x * INV_EPS - m),
                                                      __expf(x.y * INV_EPS - m));
            __nv_bfloat162 h1 = __floats2bfloat162_rn(__expf(x.z * INV_EPS - m),
                                                      __expf(x.w * INV_EPS - m));
            st.x = *(unsigned*)&h0; st.y = *(unsigned*)&h1;
        } else { st.x = 0u; st.y = 0u; }
        qh[i] = st;
    }
}

// ---------------- helpers ---------------------------------------------------
static __device__ __forceinline__ float row_dot(const __nv_bfloat16* qrow,
                                                const float4* s4, int lane)
{
    const uint4* qr = (const uint4*)qrow;
    float acc = 0.f;
    #pragma unroll
    for (int j = 0; j < 12; ++j) {
        int idx = j * 32 + lane;
        uint4 q = qr[idx];
        float4 sa = s4[idx * 2], sb = s4[idx * 2 + 1];
        float2 f0 = __bfloat1622float2(*reinterpret_cast<__nv_bfloat162*>(&q.x));
        float2 f1 = __bfloat1622float2(*reinterpret_cast<__nv_bfloat162*>(&q.y));
        float2 f2 = __bfloat1622float2(*reinterpret_cast<__nv_bfloat162*>(&q.z));
        float2 f3 = __bfloat1622float2(*reinterpret_cast<__nv_bfloat162*>(&q.w));
        acc += f0.x * sa.x + f0.y * sa.y + f1.x * sa.z + f1.y * sa.w
             + f2.x * sb.x + f2.y * sb.y + f3.x * sb.z + f3.y * sb.w;
    }
    return acc;
}

// col pass: tpart[slot][dstpar][chunk*KP + k] = sum_b scal[b] * Q[b][k]
// Called by BOTH halves every time (internal __syncthreads must match).
static __device__ __forceinline__ void col_pass(bool active, int slot, int sbid,
                                                int wtid, const float* scal,
                                                int dstpar, float* suh)
{
    bool run = active && (sbid < CTIL * NCH);      // 144 active blocks per slot
    int tile = sbid % CTIL, chunk = sbid / CTIL;
    int b0 = chunk * RPC;
    int nr = run ? min(RPC, Bn - b0) : 0;
    if (run) for (int i = wtid; i < nr; i += NT) suh[i] = scal[b0 + i];
    __syncthreads();
    if (run) {
        int k4 = tile * 1024 + wtid * 4;           // 4 bf16 cols per thread
        const uint2* qp = (const uint2*)(g_Qh[slot] + (size_t)b0 * KP + k4);
        float a0 = 0.f, a1 = 0.f, a2 = 0.f, a3 = 0.f;
        int b = 0;
        for (; b + 16 <= nr; b += 16) {            // 16 LDG.64 in flight
            #pragma unroll
            for (int j = 0; j < 16; ++j) {
                uint2 qv = qp[(size_t)j * (KP / 4)];
                float2 f0 = __bfloat1622float2(*(__nv_bfloat162*)&qv.x);
                float2 f1 = __bfloat1622float2(*(__nv_bfloat162*)&qv.y);
                float u = suh[b + j];
                a0 += u * f0.x; a1 += u * f0.y; a2 += u * f1.x; a3 += u * f1.y;
            }
            qp += (size_t)16 * (KP / 4);
        }
        for (; b < nr; ++b) {
            uint2 qv = qp[0];
            float2 f0 = __bfloat1622float2(*(__nv_bfloat162*)&qv.x);
            float2 f1 = __bfloat1622float2(*(__nv_bfloat162*)&qv.y);
            float u = suh[b];
            a0 += u * f0.x; a1 += u * f0.y; a2 += u * f1.x; a3 += u * f1.y;
            qp += KP / 4;
        }
        *(float4*)(g_tpart[slot][dstpar] + (size_t)chunk * KP + k4)
            = make_float4(a0, a1, a2, a3);
    }
}

// ---------------- fused persistent Sinkhorn (both crops, 2 halves/block) ----
__global__ __launch_bounds__(512, 1) void sinkhorn_fused()
{
    __shared__ __align__(16) float sv[2][KP];
    __shared__ float su[2][RPC + 2];
    __shared__ float swr[2][8];
    __shared__ float sqr[2][8];

    const int tid = threadIdx.x;
    const int wg = tid >> 8;           // half = slot (0: warps 0-7, 1: warps 8-15)
    const int wtid = tid & 255;
    const int lane = tid & 31;
    const int wid = wtid >> 5;
    const int slot = wg;
    const int sbid = blockIdx.x;
    const __nv_bfloat16* Qs = g_Qh[slot];

    if (sbid == 0 && wtid < 104) { g_rowerr[slot][wtid] = 0u; g_colerr[slot][wtid] = 0u; }
    grid_sync();

    bool done0 = false, done1 = false;
    int nfin0 = 100, nfin1 = 100;

    for (int iter = 1; iter <= 101; ++iter) {
        const int par = iter & 1, pprev = par ^ 1;
        const bool act = wg ? !done1 : !done0;

        // ---- v-reduce: 12 blocks/slot sum 48 chunk partials -> g_v + col err
        if (act && iter >= 2 && sbid < 12) {
            int k = sbid * 256 + wtid;
            float ce = 0.f;
            if (k < Kn) {
                float t = 0.f;
                #pragma unroll
                for (int j = 0; j < NCH; ++j) t += g_tpart[slot][pprev][(size_t)j * KP + k];
                float v = TC / (t + TINYF);
                g_v[slot][k] = v;
                ce = fabsf(v * t - TC);
            }
            #pragma unroll
            for (int o = 16; o; o >>= 1)
                ce = fmaxf(ce, __shfl_xor_sync(0xffffffffu, ce, o));
            if (lane == 0 && ce > 0.f)
                atomicMax(&g_colerr[slot][iter - 1], __float_as_uint(ce));
        }
        grid_sync();

        // ---- sv fill (sync hoisted: halves may differ in act) ----
        if (act) {
            if (iter == 1)
                for (int k = wtid; k < KP; k += NT) sv[wg][k] = (k < Kn) ? 1.f : 0.f;
            else
                for (int k = wtid; k < KP; k += NT) sv[wg][k] = (k < Kn) ? g_v[slot][k] : 0.f;
        }
        __syncthreads();

        // ---- rows: r = Q v, u = 1/(r+TINY), rowerr(iter-1) ----
        if (act) {
            float remax = 0.f;
            const float4* s4 = (const float4*)sv[wg];
            for (int row = sbid * 8 + wid; row < Bn; row += NBB * 8) {
                float acc = row_dot(Qs + (size_t)row * KP, s4, lane);
                #pragma unroll
                for (int o = 16; o; o >>= 1)
                    acc += __shfl_xor_sync(0xffffffffu, acc, o);
                if (lane == 0) {
                    g_r[slot][row] = acc;
                    g_u[slot][par][row] = 1.f / (acc + TINYF);
                    if (iter >= 2)
                        remax = fmaxf(remax, fabsf(g_u[slot][pprev][row] * acc - 1.f));
                }
            }
            if (lane == 0) swr[wg][wid] = remax;
        }
        __syncthreads();
        if (act && wtid == 0 && iter >= 2) {
            float m = swr[wg][0];
            #pragma unroll
            for (int w = 1; w < 8; ++w) m = fmaxf(m, swr[wg][w]);
            if (m > 0.f) atomicMax(&g_rowerr[slot][iter - 1], __float_as_uint(m));
        }
        grid_sync();

        // ---- convergence: same global data everywhere -> uniform decision ----
        if (iter >= 2) {
            int it = iter - 1;
            if (!done0) {
                float e = fmaxf(__uint_as_float(g_rowerr[0][it]),
                                __uint_as_float(g_colerr[0][it]));
                if (it >= 3 && (it >= 100 || e <= TOLF)) { done0 = true; nfin0 = it; }
            }
            if (!done1) {
                float e = fmaxf(__uint_as_float(g_rowerr[1][it]),
                                __uint_as_float(g_colerr[1][it]));
                if (it >= 3 && (it >= 100 || e <= TOLF)) { done1 = true; nfin1 = it; }
            }
            if (done0 && done1) break;
        }

        // ---- cols: t = u^T Q (48 deterministic chunks, uint2 loads) ----
        col_pass(wg ? !done1 : !done0, slot, sbid, wtid, g_u[slot][par], par, su[wg]);
        grid_sync();
    }

    const int nfin = wg ? nfin1 : nfin0;
    const int p = nfin & 1;

    // ---- P0: w1_b = u_b / max(u_b*r_b, TINY) ----
    if (sbid < 16) {
        int b = sbid * 256 + wtid;
        float u = g_u[slot][p][b], r = g_r[slot][b];
        g_w1[slot][b] = u / fmaxf(u * r, TINYF);
    }
    grid_sync();

    // ---- P1: column sums of row-normalized P -> tpart[1-p] ----
    col_pass(true, slot, sbid, wtid, g_w1[slot], 1 - p, su[wg]);
    grid_sync();

    // ---- beta ----
    if (sbid < 12) {
        int k = sbid * 256 + wtid;
        if (k < Kn) {
            float t = 0.f, cs = 0.f;
            #pragma unroll
            for (int j = 0; j < NCH; ++j) {
                t  += g_tpart[slot][p][(size_t)j * KP + k];
                cs += g_tpart[slot][1 - p][(size_t)j * KP + k];
            }
            float v = TC / (t + TINYF);
            float c = v * cs;
            g_beta[slot][k] = v * (TC / fmaxf(c, TINYF));
        }
    }
    grid_sync();

    // ---- P2: alpha, entropy, q_max ----
    for (int k = wtid; k < KP; k += NT)
        sv[wg][k] = (k < Kn) ? g_beta[slot][k] : 0.f;
    __syncthreads();

    float entacc = 0.f, qsum = 0.f;
    const float4* s4 = (const float4*)sv[wg];
    for (int row = sbid * 8 + wid; row < Bn; row += NBB * 8) {
        float s2 = row_dot(Qs + (size_t)row * KP, s4, lane);
        #pragma unroll
        for (int o = 16; o; o >>= 1)
            s2 += __shfl_xor_sync(0xffffffffu, s2, o);
        float w1 = g_w1[slot][row];
        float alpha = w1 / fmaxf(w1 * s2, TINYF);
        if (lane == 0) g_alpha[slot][row] = alpha;

        const uint4* qr = (const uint4*)(Qs + (size_t)row * KP);
        float qm = 0.f;
        #pragma unroll 4
        for (int j = 0; j < 12; ++j) {
            int idx = j * 32 + lane;
            uint4 q = qr[idx];
            float4 sa = s4[idx * 2], sb = s4[idx * 2 + 1];
            float2 f0 = __bfloat1622float2(*reinterpret_cast<__nv_bfloat162*>(&q.x));
            float2 f1 = __bfloat1622float2(*reinterpret_cast<__nv_bfloat162*>(&q.y));
            float2 f2 = __bfloat1622float2(*reinterpret_cast<__nv_bfloat162*>(&q.z));
            float2 f3 = __bfloat1622float2(*reinterpret_cast<__nv_bfloat162*>(&q.w));
            float pe[8] = { f0.x * sa.x, f0.y * sa.y, f1.x * sa.z, f1.y * sa.w,
                            f2.x * sb.x, f2.y * sb.y, f3.x * sb.z, f3.y * sb.w };
            #pragma unroll
            for (int e = 0; e < 8; ++e) {
                float p3 = alpha * pe[e];
                entacc += p3 * __logf(p3 + TINYF);
                qm = fmaxf(qm, p3);
            }
        }
        #pragma unroll
        for (int o = 16; o; o >>= 1)
            qm = fmaxf(qm, __shfl_xor_sync(0xffffffffu, qm, o));
        if (lane == 0) qsum += qm;
    }
    #pragma unroll
    for (int o = 16; o; o >>= 1)
        entacc += __shfl_xor_sync(0xffffffffu, entacc, o);
    __syncthreads();
    if (lane == 0) { swr[wg][wid] = entacc; sqr[wg][wid] = qsum; }
    __syncthreads();
    if (wtid == 0) {
        float e = 0.f, q = 0.f;
        #pragma unroll
        for (int w = 0; w < 8; ++w) { e += swr[wg][w]; q += sqr[wg][w]; }
        atomicAdd(&g_ent[slot], e);
        atomicAdd(&g_qmax[slot], q);
    }
}

// ---------------- loss over all 8 crops (vectorized) ------------------------
__global__ __launch_bounds__(NT) void loss_kernel(Ptrs ptrs, const int* pia, const int* pib)
{
    __shared__ __align__(16) float pa[Kn];
    __shared__ __align__(16) float pb[Kn];
    __shared__ float wtmp[8];
    __shared__ float ws0[8], ws1[8], ws2[8];
    int b = blockIdx.x, tid = threadIdx.x;
    int lane = tid & 31, wid = tid >> 5;
    int ia = *pia, ib = *pib;

    float aA = g_alpha[0][b], aB = g_alpha[1][b];
    const uint2* q0 = (const uint2*)(g_Qh[0] + (size_t)b * KP);
    const uint2* q1 = (const uint2*)(g_Qh[1] + (size_t)b * KP);
    const float4* be0 = (const float4*)g_beta[0];
    const float4* be1 = (const float4*)g_beta[1];
    for (int i = tid; i < Kn / 4; i += NT) {
        uint2 v0 = q0[i], v1 = q1[i];
        float4 b0 = be0[i], b1 = be1[i];
        float2 f00 = __bfloat1622float2(*(__nv_bfloat162*)&v0.x);
        float2 f01 = __bfloat1622float2(*(__nv_bfloat162*)&v0.y);
        float2 f10 = __bfloat1622float2(*(__nv_bfloat162*)&v1.x);
        float2 f11 = __bfloat1622float2(*(__nv_bfloat162*)&v1.y);
        ((float4*)pa)[i] = make_float4(aA * f00.x * b0.x, aA * f00.y * b0.y,
                                       aA * f01.x * b0.z, aA * f01.y * b0.w);
        ((float4*)pb)[i] = make_float4(aB * f10.x * b1.x, aB * f10.y * b1.y,
                                       aB * f11.x * b1.z, aB * f11.y * b1.w);
    }
    __syncthreads();

    float accLoss = 0.f;
    for (int c = 0; c < 8; ++c) {
        const float4* lr4 = (const float4*)(ptrs.p[c] + (size_t)b * Kn);
        float mx = -3.4e38f;
        for (int i = tid; i < Kn / 4; i += NT) {
            float4 x = lr4[i];
            mx = fmaxf(mx, fmaxf(fmaxf(x.x, x.y), fmaxf(x.z, x.w)));
        }
        #pragma unroll
        for (int o = 16; o; o >>= 1) mx = fmaxf(mx, __shfl_xor_sync(0xffffffffu, mx, o));
        if (lane == 0) wtmp[wid] = mx;
        __syncthreads();
        float bm = wtmp[0];
        #pragma unroll
        for (int w = 1; w < 8; ++w) bm = fmaxf(bm, wtmp[w]);

        float se = 0.f, da = 0.f, db = 0.f;
        for (int i = tid; i < Kn / 4; i += NT) {
            float4 x = lr4[i];
            se += __expf(INV_TEMP * (x.x - bm)) + __expf(INV_TEMP * (x.y - bm))
                + __expf(INV_TEMP * (x.z - bm)) + __expf(INV_TEMP * (x.w - bm));
            float4 pav = ((const float4*)pa)[i];
            float4 pbv = ((const float4*)pb)[i];
            da += pav.x * x.x + pav.y * x.y + pav.z * x.z + pav.w * x.w;
            db += pbv.x * x.x + pbv.y * x.y + pbv.z * x.z + pbv.w * x.w;
        }
        #pragma unroll
        for (int o = 16; o; o >>= 1) {
            se += __shfl_xor_sync(0xffffffffu, se, o);
            da += __shfl_xor_sync(0xffffffffu, da, o);
            db += __shfl_xor_sync(0xffffffffu, db, o);
        }
        if (lane == 0) { ws0[wid] = se; ws1[wid] = da; ws2[wid] = db; }
        __syncthreads();
        if (tid == 0) {
            float st = 0.f, dat = 0.f, dbt = 0.f;
            #pragma unroll
            for (int w = 0; w < 8; ++w) { st += ws0[w]; dat += ws1[w]; dbt += ws2[w]; }
            float lse = INV_TEMP * bm + __logf(st);
            if (c != ia) accLoss += INV_TEMP * dat - lse;
            if (c != ib) accLoss += INV_TEMP * dbt - lse;
        }
        __syncthreads();
    }
    if (tid == 0) atomicAdd(&g_loss, accLoss);
}

// ---------------- finalize --------------------------------------------------
__global__ void finalize_kernel(float* out, int out_size)
{
    if (threadIdx.x == 0) {
        float loss = -g_loss / (14.f * (float)Bn);
        float ent  = -0.5f * (g_ent[0] + g_ent[1]) / (float)Bn;
        float qm   =  0.5f * (g_qmax[0] + g_qmax[1]) / (float)Bn;
        if (out_size > 0) out[0] = loss;
        if (out_size > 1) out[1] = ent;
        if (out_size > 2) out[2] = qm;
    }
}

// ---------------- launcher --------------------------------------------------
extern "C" void kernel_launch(void* const* d_in, const int* in_sizes, int n_in,
                              void* d_out, int out_size)
{
    (void)in_sizes; (void)n_in;
    Ptrs ptrs;
    for (int i = 0; i < 8; ++i) ptrs.p[i] = (const float*)d_in[i];
    const int* ia = (const int*)d_in[8];
    const int* ib = (const int*)d_in[9];

    init_kernel<<<1, 32>>>();
    prep_kernel<<<2 * Bn, NT>>>(ptrs, ia, ib);
    sinkhorn_fused<<<NBB, 512>>>();
    loss_kernel<<<Bn, NT>>>(ptrs, ia, ib);
    finalize_kernel<<<1, 32>>>((float*)d_out, out_size);
}